// round 16
// baseline (speedup 1.0000x reference)
#include <cuda_runtime.h>
#include <cuda_bf16.h>
#include <cstdint>

// ---------------- device scratch (no allocations allowed) -------------------
__device__ float g_h2[256 * 64];     // layer-2 final hidden [B][64]

// ---------------- SMEM map (dynamic) -----------------------------------------
#define W1T   0
#define V1O   196608                  // [8 n][200 bf16] rows padded to 400B
#define V2O   (196608 + 3200)         // [8 n][200 bf16]
#define SG1   (196608 + 6400)         // [512 rows][2 batches] f32 = 4096B
#define SG2   (SG1 + 4096)            // [256 rows][2 batches] f32 = 2048B
#define SMEMSZ (SG2 + 2048)           // 209152 B

#define VROW  400                     // bytes per V row (bank stride 4 -> conflict-free)
#define NTHR  512

// ---------------- helpers ---------------------------------------------------
static __device__ __forceinline__ uint32_t smem_u32(const void* p) {
    uint32_t a;
    asm("{ .reg .u64 t; cvta.to.shared.u64 t, %1; cvt.u32.u64 %0, t; }" : "=r"(a) : "l"(p));
    return a;
}
static __device__ __forceinline__ float fast_rcp(float x) {
    float r; asm("rcp.approx.f32 %0,%1;" : "=f"(r) : "f"(x)); return r;
}
static __device__ __forceinline__ float sigmoid_f(float x) { return fast_rcp(1.f + __expf(-x)); }
static __device__ __forceinline__ float tanh_f(float x)    { return 1.f - 2.f * fast_rcp(1.f + __expf(2.f * x)); }

static __device__ __forceinline__ uint32_t packbf(float a, float b) {
    __nv_bfloat162 t = __floats2bfloat162_rn(a, b);
    return *(uint32_t*)&t;
}

#define LDSM_X4(a0, a1, a2, a3, addr) \
    asm volatile("ldmatrix.sync.aligned.m8n8.x4.shared.b16 {%0,%1,%2,%3}, [%4];" \
                 : "=r"(a0), "=r"(a1), "=r"(a2), "=r"(a3) : "r"(addr))

#define HMMA(c0, c1, c2, c3, a0, a1, a2, a3, b0, b1) \
    asm volatile("mma.sync.aligned.m16n8k16.row.col.f32.bf16.bf16.f32 " \
                 "{%0,%1,%2,%3}, {%4,%5,%6,%7}, {%8,%9}, {%0,%1,%2,%3};" \
                 : "+f"(c0), "+f"(c1), "+f"(c2), "+f"(c3) \
                 : "r"(a0), "r"(a1), "r"(a2), "r"(a3), "r"(b0), "r"(b1))

static __device__ __forceinline__ uint32_t lds32(uint32_t addr) {
    uint32_t v; asm volatile("ld.shared.b32 %0, [%1];" : "=r"(v) : "r"(addr)); return v;
}

// ---------------- fused persistent LSTM (pipelined, HMMA, 16 warps) ---------
// 128 CTAs x 512 threads (16 warps, 4/SMSP for LDSM latency hiding).
// CTA owns batches (2*bid, 2*bid+1). Per iteration s: ONE MMA phase
// (L1 t=s: 2 mtiles/warp via LDSM; L2 t=s-1: 1 mtile/warp, reg W2 frags),
// then ONE update phase: h1(s) | h2(s-1) | x(s+1) staging.
__global__ void __launch_bounds__(NTHR, 1) lstm_fused_kernel(
    const float* __restrict__ x,
    const float* __restrict__ Wih1, const float* __restrict__ Whh1,
    const float* __restrict__ bih1, const float* __restrict__ bhh1,
    const float* __restrict__ Wih2, const float* __restrict__ Whh2,
    const float* __restrict__ bih2, const float* __restrict__ bhh2)
{
    extern __shared__ __align__(128) char smem[];
    const int tid  = threadIdx.x;
    const int wid  = tid >> 5;
    const int lane = tid & 31;
    const int gid  = lane >> 2;        // 0..7
    const int tid4 = lane & 3;         // 0..3
    const int b0   = blockIdx.x * 2;
    const uint32_t sb = smem_u32(smem);

    // ---- stage W1 -> SMEM bf16 in ldmatrix-block tile layout
    for (int idx = tid; idx < 49152; idx += NTHR) {
        int R = idx / 96, kp = idx % 96, k0 = 2 * kp;
        float w0, w1;
        if (k0 < 64) { w0 = Wih1[R * 64 + k0];       w1 = Wih1[R * 64 + k0 + 1]; }
        else         { w0 = Whh1[R * 128 + k0 - 64]; w1 = Whh1[R * 128 + k0 - 63]; }
        int mt = R >> 4, kt = k0 >> 4, rr = R & 15, kk = k0 & 15;
        int blk = ((kk >> 3) << 1) | (rr >> 3);
        uint32_t off = (uint32_t)((mt * 12 + kt) * 4 + blk) * 128u
                     + (uint32_t)(rr & 7) * 16u + (uint32_t)(kk & 7) * 2u;
        *(uint32_t*)(smem + W1T + off) = packbf(w0, w1);
    }

    // ---- zero V1 + V2 (contiguous 6400 B)
    for (int i = tid; i < 6400 / 4; i += NTHR) ((uint32_t*)(smem + V1O))[i] = 0;

    // ---- W2 A-fragments -> registers (1 mtile per warp, 12 ktiles, 4 regs)
    uint32_t wf[12][4];
    {
        int r = wid * 16 + gid;
        #pragma unroll
        for (int kt = 0; kt < 12; kt++) {
            int c = kt * 16 + tid4 * 2;
            #pragma unroll
            for (int q = 0; q < 4; q++) {
                int rr = r + ((q & 1) ? 8 : 0);
                int cc = c + ((q & 2) ? 8 : 0);
                float v0 = (cc < 128) ? Wih2[rr * 128 + cc]     : Whh2[rr * 64 + cc - 128];
                float v1 = (cc + 1 < 128) ? Wih2[rr * 128 + cc + 1] : Whh2[rr * 64 + cc - 127];
                wf[kt][q] = packbf(v0, v1);
            }
        }
    }

    // ---- biases (role-split)
    float b1i = 0, b1f = 0, b1g = 0, b1o = 0;
    if (tid < 128) {
        b1i = bih1[tid] + bhh1[tid];
        b1f = bih1[128 + tid] + bhh1[128 + tid];
        b1g = bih1[256 + tid] + bhh1[256 + tid];
        b1o = bih1[384 + tid] + bhh1[384 + tid];
    }
    float b2i = 0, b2f = 0, b2g = 0, b2o = 0;
    if (tid >= 128 && tid < 192) {
        int j = tid - 128;
        b2i = bih2[j] + bhh2[j];
        b2f = bih2[64 + j] + bhh2[64 + j];
        b2g = bih2[128 + j] + bhh2[128 + j];
        b2o = bih2[192 + j] + bhh2[192 + j];
    }

    __syncthreads();   // zeroing complete before x(0) staging

    // ---- x staging role (tid 192..255): thread owns col k, both batches
    const int xk = tid - 192;
    if (tid >= 192 && tid < 256) {
        *(__nv_bfloat16*)(smem + V1O + 0 * VROW + xk * 2) =
            __float2bfloat16(x[((b0 + 0) * 1024 + 0) * 64 + xk]);
        *(__nv_bfloat16*)(smem + V1O + 1 * VROW + xk * 2) =
            __float2bfloat16(x[((b0 + 1) * 1024 + 0) * 64 + xk]);
    }

    __syncthreads();   // W1 staged, V zeroed, x(0) in place

    float* sg1 = (float*)(smem + SG1);
    float* sg2 = (float*)(smem + SG2);
    const uint32_t v1u = sb + V1O + (uint32_t)gid * VROW + (uint32_t)tid4 * 4;
    const uint32_t v2u = sb + V2O + (uint32_t)gid * VROW + (uint32_t)tid4 * 4;
    const uint32_t w1u = sb + W1T + 128u * (uint32_t)(lane >> 3) + 16u * (uint32_t)(lane & 7);

    float c1a = 0.f, c1b = 0.f;            // L1 cell (tid<128: hidden j = tid)
    float c2a = 0.f, c2b = 0.f;            // L2 cell (tid 128..191: hidden j = tid-128)
    float h2a = 0.f, h2b = 0.f;

    #pragma unroll 1
    for (int s = 0; s < 1025; s++) {
        // prefetch x(s+1)
        float xpa = 0.f, xpb = 0.f;
        if (tid >= 192 && tid < 256 && s + 1 < 1024) {
            xpa = x[((b0 + 0) * 1024 + (s + 1)) * 64 + xk];
            xpb = x[((b0 + 1) * 1024 + (s + 1)) * 64 + xk];
        }

        // ---- Phase A: L2 HMMA (t=s-1, 1 mtile, reg A-frags) + L1 HMMA (t=s, 2 mtiles)
        {
            // L2: gates from V2 = [h1(s-1) | h2(s-2)]
            uint32_t e0[12], e1[12];
            #pragma unroll
            for (int kt = 0; kt < 12; kt++) {
                e0[kt] = lds32(v2u + (uint32_t)kt * 32u);
                e1[kt] = lds32(v2u + (uint32_t)kt * 32u + 16u);
            }
            {
                float d0 = 0.f, d1 = 0.f, d2 = 0.f, d3 = 0.f;
                #pragma unroll
                for (int kt = 0; kt < 12; kt++)
                    HMMA(d0, d1, d2, d3, wf[kt][0], wf[kt][1],
                         wf[kt][2], wf[kt][3], e0[kt], e1[kt]);
                if (tid4 == 0) {
                    int row = wid * 16 + gid;
                    *(float2*)(sg2 + 2 * row)       = make_float2(d0, d1);
                    *(float2*)(sg2 + 2 * (row + 8)) = make_float2(d2, d3);
                }
            }

            // L1: gates from V1 = [x(s) | h1(s-1)]
            if (s < 1024) {
                uint32_t f0[12], f1[12];
                #pragma unroll
                for (int kt = 0; kt < 12; kt++) {
                    f0[kt] = lds32(v1u + (uint32_t)kt * 32u);
                    f1[kt] = lds32(v1u + (uint32_t)kt * 32u + 16u);
                }
                #pragma unroll
                for (int i = 0; i < 2; i++) {
                    const int mt = wid * 2 + i;
                    float c0 = 0.f, c1 = 0.f, c2 = 0.f, c3 = 0.f;
                    const uint32_t abase = w1u + (uint32_t)(mt * 12) * 512u;
                    #pragma unroll
                    for (int kt = 0; kt < 12; kt++) {
                        uint32_t a0, a1, a2, a3;
                        LDSM_X4(a0, a1, a2, a3, abase + (uint32_t)kt * 512u);
                        HMMA(c0, c1, c2, c3, a0, a1, a2, a3, f0[kt], f1[kt]);
                    }
                    if (tid4 == 0) {
                        int row = mt * 16 + gid;
                        *(float2*)(sg1 + 2 * row)       = make_float2(c0, c1);
                        *(float2*)(sg1 + 2 * (row + 8)) = make_float2(c2, c3);
                    }
                }
            }
        }
        __syncthreads();

        // ---- Phase B: h1(s) | h2(s-1) | x(s+1) staging, concurrently
        if (tid < 128) {
            if (s < 1024) {
                const int j = tid;
                float2 gi = *(float2*)(sg1 + 2 * j);
                float2 gf = *(float2*)(sg1 + 2 * (128 + j));
                float2 gg = *(float2*)(sg1 + 2 * (256 + j));
                float2 go = *(float2*)(sg1 + 2 * (384 + j));
                {
                    float ig = sigmoid_f(gi.x + b1i);
                    float fg = sigmoid_f(gf.x + b1f);
                    float gv = tanh_f(gg.x + b1g);
                    float og = sigmoid_f(go.x + b1o);
                    c1a = fg * c1a + ig * gv;
                    __nv_bfloat16 h = __float2bfloat16(og * tanh_f(c1a));
                    *(__nv_bfloat16*)(smem + V1O + 0 * VROW + (64 + j) * 2) = h;
                    *(__nv_bfloat16*)(smem + V2O + 0 * VROW + j * 2)        = h;
                }
                {
                    float ig = sigmoid_f(gi.y + b1i);
                    float fg = sigmoid_f(gf.y + b1f);
                    float gv = tanh_f(gg.y + b1g);
                    float og = sigmoid_f(go.y + b1o);
                    c1b = fg * c1b + ig * gv;
                    __nv_bfloat16 h = __float2bfloat16(og * tanh_f(c1b));
                    *(__nv_bfloat16*)(smem + V1O + 1 * VROW + (64 + j) * 2) = h;
                    *(__nv_bfloat16*)(smem + V2O + 1 * VROW + j * 2)        = h;
                }
            }
        } else if (tid < 192) {
            if (s > 0) {
                const int j = tid - 128;
                float2 gi = *(float2*)(sg2 + 2 * j);
                float2 gf = *(float2*)(sg2 + 2 * (64 + j));
                float2 gg = *(float2*)(sg2 + 2 * (128 + j));
                float2 go = *(float2*)(sg2 + 2 * (192 + j));
                {
                    float ig = sigmoid_f(gi.x + b2i);
                    float fg = sigmoid_f(gf.x + b2f);
                    float gv = tanh_f(gg.x + b2g);
                    float og = sigmoid_f(go.x + b2o);
                    c2a = fg * c2a + ig * gv;
                    h2a = og * tanh_f(c2a);
                    *(__nv_bfloat16*)(smem + V2O + 0 * VROW + (128 + j) * 2) = __float2bfloat16(h2a);
                }
                {
                    float ig = sigmoid_f(gi.y + b2i);
                    float fg = sigmoid_f(gf.y + b2f);
                    float gv = tanh_f(gg.y + b2g);
                    float og = sigmoid_f(go.y + b2o);
                    c2b = fg * c2b + ig * gv;
                    h2b = og * tanh_f(c2b);
                    *(__nv_bfloat16*)(smem + V2O + 1 * VROW + (128 + j) * 2) = __float2bfloat16(h2b);
                }
            }
        } else if (tid < 256) {
            if (s + 1 < 1024) {
                *(__nv_bfloat16*)(smem + V1O + 0 * VROW + xk * 2) = __float2bfloat16(xpa);
                *(__nv_bfloat16*)(smem + V1O + 1 * VROW + xk * 2) = __float2bfloat16(xpb);
            }
        }
        __syncthreads();
    }

    if (tid >= 128 && tid < 192) {
        const int j = tid - 128;
        g_h2[(b0 + 0) * 64 + j] = h2a;
        g_h2[(b0 + 1) * 64 + j] = h2b;
    }
}

// ---------------- MLP head ----------------------------------------------------
__global__ void __launch_bounds__(256, 1) mlp_kernel(
    const float* __restrict__ W1, const float* __restrict__ b1,
    const float* __restrict__ W2, const float* __restrict__ b2,
    float* __restrict__ out)
{
    __shared__ float sW1[32 * 64];
    __shared__ float sb1[32];
    __shared__ float sW2[32];
    __shared__ float sb2;
    const int tid = threadIdx.x;
    for (int i = tid; i < 2048; i += 256) sW1[i] = W1[i];
    if (tid < 32) { sb1[tid] = b1[tid]; sW2[tid] = W2[tid]; }
    if (tid == 0) sb2 = b2[0];
    __syncthreads();

    float hv[64];
    #pragma unroll
    for (int k = 0; k < 16; k++)
        *(float4*)&hv[4 * k] = *(const float4*)&g_h2[tid * 64 + 4 * k];

    float acc = 0.0f;
    #pragma unroll 1
    for (int m = 0; m < 32; m++) {
        float d = sb1[m];
        #pragma unroll
        for (int k = 0; k < 64; k++) d += sW1[m * 64 + k] * hv[k];
        acc += sW2[m] * sigmoid_f(d);
    }
    out[tid] = sigmoid_f(acc + sb2);
}

// ---------------- launch ------------------------------------------------------
extern "C" void kernel_launch(void* const* d_in, const int* in_sizes, int n_in,
                              void* d_out, int out_size)
{
    const float* x    = (const float*)d_in[0];
    const float* Wih1 = (const float*)d_in[1];
    const float* Whh1 = (const float*)d_in[2];
    const float* bih1 = (const float*)d_in[3];
    const float* bhh1 = (const float*)d_in[4];
    const float* Wih2 = (const float*)d_in[5];
    const float* Whh2 = (const float*)d_in[6];
    const float* bih2 = (const float*)d_in[7];
    const float* bhh2 = (const float*)d_in[8];
    const float* W1   = (const float*)d_in[9];
    const float* b1   = (const float*)d_in[10];
    const float* W2   = (const float*)d_in[11];
    const float* b2   = (const float*)d_in[12];
    float* out = (float*)d_out;

    cudaFuncSetAttribute(lstm_fused_kernel,
                         cudaFuncAttributeMaxDynamicSharedMemorySize, SMEMSZ);

    lstm_fused_kernel<<<128, NTHR, SMEMSZ>>>(x, Wih1, Whh1, bih1, bhh1,
                                             Wih2, Whh2, bih2, bhh2);
    mlp_kernel<<<1, 256>>>(W1, b1, W2, b2, out);
}